// round 5
// baseline (speedup 1.0000x reference)
#include <cuda_runtime.h>

// Problem constants (fixed by setup_inputs)
#define S_LEN 4096
#define BATCH 8
#define DIM 1024
#define D4 (DIM / 4)          // 256 float4 per row
#define SPLIT 49
#define SCALE 32.0f           // sqrt(1024)

// Grid = 1184 blocks = one wave on 148 SMs at 8 CTAs/SM.
//   blockIdx 0        : doc segmented-count scan (first wave, fully hidden)
//   blockIdx 1..1183  : grid-stride over QUARTER-TOKEN units (2 batch rows).
//
// Per unit: both emb loads issued back-to-back (MLP=2 per warp) before the
// stores. 64 warps/SM x 2 x 128B = 16KB in flight per SM > ~11.5KB needed to
// saturate DRAM at ~380cyc effective latency. 16384 units / 1183 blocks ->
// max/mean imbalance 1.01. pe row read by 4 blocks; repeats are L2 hits.
#define EW_BLOCKS 1183
#define N_UNITS (S_LEN * 4)

__global__ __launch_bounds__(256, 8)
void pe_fused_kernel(const float4* __restrict__ emb,
                     const int*    __restrict__ src,
                     const float4* __restrict__ pe,
                     float4*       __restrict__ out,
                     float*        __restrict__ doc)
{
    const int blk = blockIdx.x;

    if (blk > 0) {
        const int d = threadIdx.x;           // 0..255
        for (int u = blk - 1; u < N_UNITS; u += EW_BLOCKS) {
            const int t   = u >> 2;
            const int b0  = (u & 3) * 2;
            const int idx0 = (t * BATCH + b0) * D4 + d;
            const int idx1 = idx0 + D4;

            // Two independent loads in flight, then pe, then stores.
            const float4 e0 = __ldcs(&emb[idx0]);
            const float4 e1 = __ldcs(&emb[idx1]);
            const float4 p  = __ldg(&pe[t * D4 + d]);

            float4 o0, o1;
            o0.x = fmaf(e0.x, SCALE, p.x);
            o0.y = fmaf(e0.y, SCALE, p.y);
            o0.z = fmaf(e0.z, SCALE, p.z);
            o0.w = fmaf(e0.w, SCALE, p.w);
            __stcs(&out[idx0], o0);

            o1.x = fmaf(e1.x, SCALE, p.x);
            o1.y = fmaf(e1.y, SCALE, p.y);
            o1.z = fmaf(e1.z, SCALE, p.z);
            o1.w = fmaf(e1.w, SCALE, p.w);
            __stcs(&out[idx1], o1);
        }
        return;
    }

    // ---- doc scan block (blockIdx 0, first wave, overlapped) ----
    __shared__ unsigned words[BATCH * 128];  // 4096 bits per column

    const int warp = threadIdx.x >> 5;       // batch column 0..7
    const int lane = threadIdx.x & 31;

    // Pass 1: build flag bitmasks
    #pragma unroll 8
    for (int c = 0; c < 128; c++) {
        const int t = c * 32 + lane;
        const int v = __ldg(&src[t * BATCH + warp]);
        unsigned m = __ballot_sync(0xFFFFFFFFu, v == SPLIT);
        if (lane == 0) words[warp * 128 + c] = m;
    }
    __syncwarp();

    // Pass 2: inclusive popc-scan with carry; zero positions whose next
    // position is a split token.
    int carry = 0;
    const unsigned le_mask = 0xFFFFFFFFu >> (31 - lane);
    for (int c = 0; c < 128; c++) {
        const unsigned m = words[warp * 128 + c];
        const int t = c * 32 + lane;
        const int incl = carry + __popc(m & le_mask);

        unsigned next_bit;
        if (lane < 31)
            next_bit = (m >> (lane + 1)) & 1u;
        else
            next_bit = (c < 127) ? (words[warp * 128 + c + 1] & 1u) : 0u;

        doc[t * BATCH + warp] = next_bit ? 0.0f : (float)incl;
        carry += __popc(m);
    }
}

extern "C" void kernel_launch(void* const* d_in, const int* in_sizes, int n_in,
                              void* d_out, int out_size)
{
    const float* emb = (const float*)d_in[0];   // [S, B, DIM] f32
    const int*   src = (const int*)  d_in[1];   // [S, B, 1]   i32
    const float* pe  = (const float*)d_in[2];   // [5000, 1, DIM] f32

    float* out = (float*)d_out;                  // first in_sizes[0] floats
    float* doc = out + (size_t)in_sizes[0];      // then S*B floats

    pe_fused_kernel<<<EW_BLOCKS + 1, 256>>>(
        (const float4*)emb, src, (const float4*)pe,
        (float4*)out, doc);
}

// round 6
// speedup vs baseline: 1.0880x; 1.0880x over previous
#include <cuda_runtime.h>

// Problem constants (fixed by setup_inputs)
#define S_LEN 4096
#define BATCH 8
#define DIM 1024
#define D4 (DIM / 4)          // 256 float4 per row
#define SPLIT 49
#define SCALE 32.0f           // sqrt(1024)

// Grid = 592 blocks x 512 threads = one wave on 148 SMs at 4 CTAs/SM
// (64 warps/SM, same as R4).
//   blockIdx 0       : doc segmented-count scan (first wave, fully hidden)
//   blockIdx 1..591  : grid-stride over WHOLE tokens; 4096/591 = 6.93
//                      (max/mean imbalance 1.01).
//
// Thread (h,d): h = tid>>8 in {0,1}, d = tid&255. Handles rows b0+h for
// b0 = 0,2,4,6. pe[t,d] loaded once per token; the two h-halves hit the
// same L1 line. Inner loop keeps R4's winning interleaved
// ldcs -> fma -> stcs (MLP=1) shape.
#define EW_BLOCKS 591

__global__ __launch_bounds__(512, 4)
void pe_fused_kernel(const float4* __restrict__ emb,
                     const int*    __restrict__ src,
                     const float4* __restrict__ pe,
                     float4*       __restrict__ out,
                     float*        __restrict__ doc)
{
    const int blk = blockIdx.x;

    if (blk > 0) {
        const int d = threadIdx.x & 255;     // float4 column 0..255
        const int h = threadIdx.x >> 8;      // batch-half 0..1
        for (int t = blk - 1; t < S_LEN; t += EW_BLOCKS) {
            const float4 p = __ldg(&pe[t * D4 + d]);
            #pragma unroll
            for (int b0 = 0; b0 < BATCH; b0 += 2) {
                const int idx = (t * BATCH + b0 + h) * D4 + d;
                float4 e = __ldcs(&emb[idx]);
                float4 o;
                o.x = fmaf(e.x, SCALE, p.x);
                o.y = fmaf(e.y, SCALE, p.y);
                o.z = fmaf(e.z, SCALE, p.z);
                o.w = fmaf(e.w, SCALE, p.w);
                __stcs(&out[idx], o);
            }
        }
        return;
    }

    // ---- doc scan block (blockIdx 0, warps 0-7 only; warps 8-15 exit) ----
    __shared__ unsigned words[BATCH * 128];  // 4096 bits per column

    if (threadIdx.x >= 256) return;

    const int warp = threadIdx.x >> 5;       // batch column 0..7
    const int lane = threadIdx.x & 31;

    // Pass 1: build flag bitmasks
    #pragma unroll 8
    for (int c = 0; c < 128; c++) {
        const int t = c * 32 + lane;
        const int v = __ldg(&src[t * BATCH + warp]);
        unsigned m = __ballot_sync(0xFFFFFFFFu, v == SPLIT);
        if (lane == 0) words[warp * 128 + c] = m;
    }
    __syncwarp();

    // Pass 2: inclusive popc-scan with carry; zero positions whose next
    // position is a split token.
    int carry = 0;
    const unsigned le_mask = 0xFFFFFFFFu >> (31 - lane);
    for (int c = 0; c < 128; c++) {
        const unsigned m = words[warp * 128 + c];
        const int t = c * 32 + lane;
        const int incl = carry + __popc(m & le_mask);

        unsigned next_bit;
        if (lane < 31)
            next_bit = (m >> (lane + 1)) & 1u;
        else
            next_bit = (c < 127) ? (words[warp * 128 + c + 1] & 1u) : 0u;

        doc[t * BATCH + warp] = next_bit ? 0.0f : (float)incl;
        carry += __popc(m);
    }
}

extern "C" void kernel_launch(void* const* d_in, const int* in_sizes, int n_in,
                              void* d_out, int out_size)
{
    const float* emb = (const float*)d_in[0];   // [S, B, DIM] f32
    const int*   src = (const int*)  d_in[1];   // [S, B, 1]   i32
    const float* pe  = (const float*)d_in[2];   // [5000, 1, DIM] f32

    float* out = (float*)d_out;                  // first in_sizes[0] floats
    float* doc = out + (size_t)in_sizes[0];      // then S*B floats

    pe_fused_kernel<<<EW_BLOCKS + 1, 512>>>(
        (const float4*)emb, src, (const float4*)pe,
        (float4*)out, doc);
}